// round 2
// baseline (speedup 1.0000x reference)
#include <cuda_runtime.h>

#define NTOK 8192
#define CCH  64

// Scratch (allocation-free rule: __device__ globals)
__device__ float d_F [2 * NTOK * 8];   // f[n,0..7] per input
__device__ float d_GT[2 * NTOK * 8];   // g^T: gt[m,0..7] per input
__device__ float d_VT[2 * NTOK * 64];  // v^T: vt[n,c] per input
__device__ float d_invden[2 * NTOK];   // 1 / softmax denominator per row n

// ---------------------------------------------------------------------------
// Kernel 1: projections f = Wf x + bf, g = Wg x + bg, v = Wh x + bh
// grid (64, 2), block 128. Each thread owns one token n (all 64 channels in regs).
// ---------------------------------------------------------------------------
__global__ __launch_bounds__(128) void proj_kernel(
    const float* __restrict__ x1, const float* __restrict__ x2,
    const float* __restrict__ Wf, const float* __restrict__ bf,
    const float* __restrict__ Wg, const float* __restrict__ bg,
    const float* __restrict__ Wh1, const float* __restrict__ bh1,
    const float* __restrict__ Wh2, const float* __restrict__ bh2)
{
    const int input = blockIdx.y;
    const float* __restrict__ x  = input ? x2  : x1;
    const float* __restrict__ Wh = input ? Wh2 : Wh1;
    const float* __restrict__ bh = input ? bh2 : bh1;

    __shared__ float Wf_s[8 * 64], Wg_s[8 * 64], Wh_s[64 * 64];
    __shared__ float bf_s[8], bg_s[8], bh_s[64];
    __shared__ float v_s[32][129];  // half of v, padded (stride 129 -> conflict-free)

    const int tid = threadIdx.x;
    for (int i = tid; i < 8 * 64; i += 128) { Wf_s[i] = Wf[i]; Wg_s[i] = Wg[i]; }
    for (int i = tid; i < 64 * 64; i += 128) Wh_s[i] = Wh[i];
    if (tid < 8)  { bf_s[tid] = bf[tid]; bg_s[tid] = bg[tid]; }
    if (tid < 64) bh_s[tid] = bh[tid];
    __syncthreads();

    const int base = blockIdx.x * 128;
    const int n = base + tid;

    float xr[64];
    #pragma unroll
    for (int c = 0; c < 64; c++) xr[c] = x[c * NTOK + n];

    // f and g (8 outputs each)
    float fo[8], go[8];
    #pragma unroll
    for (int o = 0; o < 8; o++) {
        float af = bf_s[o], ag = bg_s[o];
        const float4* wf4 = (const float4*)&Wf_s[o * 64];
        const float4* wg4 = (const float4*)&Wg_s[o * 64];
        #pragma unroll
        for (int q = 0; q < 16; q++) {
            float4 wfv = wf4[q], wgv = wg4[q];
            af = fmaf(wfv.x, xr[4*q+0], af); af = fmaf(wfv.y, xr[4*q+1], af);
            af = fmaf(wfv.z, xr[4*q+2], af); af = fmaf(wfv.w, xr[4*q+3], af);
            ag = fmaf(wgv.x, xr[4*q+0], ag); ag = fmaf(wgv.y, xr[4*q+1], ag);
            ag = fmaf(wgv.z, xr[4*q+2], ag); ag = fmaf(wgv.w, xr[4*q+3], ag);
        }
        fo[o] = af; go[o] = ag;
    }
    {
        float4* Fo = (float4*)&d_F [(size_t)(input * NTOK + n) * 8];
        float4* Go = (float4*)&d_GT[(size_t)(input * NTOK + n) * 8];
        Fo[0] = make_float4(fo[0], fo[1], fo[2], fo[3]);
        Fo[1] = make_float4(fo[4], fo[5], fo[6], fo[7]);
        Go[0] = make_float4(go[0], go[1], go[2], go[3]);
        Go[1] = make_float4(go[4], go[5], go[6], go[7]);
    }

    // v (64 outputs), in two halves to fit static smem; transpose via shared
    #pragma unroll
    for (int half = 0; half < 2; half++) {
        #pragma unroll
        for (int o2 = 0; o2 < 32; o2++) {
            const int o = half * 32 + o2;
            float a = bh_s[o];
            const float4* wh4 = (const float4*)&Wh_s[o * 64];
            #pragma unroll
            for (int q = 0; q < 16; q++) {
                float4 w = wh4[q];
                a = fmaf(w.x, xr[4*q+0], a); a = fmaf(w.y, xr[4*q+1], a);
                a = fmaf(w.z, xr[4*q+2], a); a = fmaf(w.w, xr[4*q+3], a);
            }
            v_s[o2][tid] = a;
        }
        __syncthreads();
        // coalesced transpose write-out: VT[n][c]
        for (int i = tid; i < 128 * 32; i += 128) {
            const int nl = i >> 5, o2 = i & 31;
            d_VT[(size_t)(input * NTOK + base + nl) * 64 + half * 32 + o2] = v_s[o2][nl];
        }
        __syncthreads();
    }
}

// ---------------------------------------------------------------------------
// Kernel 2: den[n] = sum_m exp(f[n] . gt[m]); store 1/den.
// grid (128, 2), block 256: 64 n per block, 4 threads per n splitting m.
// ---------------------------------------------------------------------------
__global__ __launch_bounds__(256) void passA_kernel()
{
    const int input = blockIdx.y;
    const int tid = threadIdx.x;
    const int nl = tid >> 2, sub = tid & 3;
    const int n = blockIdx.x * 64 + nl;

    const float4* F4  = (const float4*)d_F;
    const float4* GT4 = (const float4*)d_GT;
    const float4 fa = F4[(size_t)(input * NTOK + n) * 2 + 0];
    const float4 fb = F4[(size_t)(input * NTOK + n) * 2 + 1];

    __shared__ float4 gt_s[64][2];

    float acc = 0.f;
    for (int m0 = 0; m0 < NTOK; m0 += 64) {
        __syncthreads();
        if (tid < 128) {
            gt_s[tid >> 1][tid & 1] =
                GT4[(size_t)(input * NTOK + m0 + (tid >> 1)) * 2 + (tid & 1)];
        }
        __syncthreads();
        #pragma unroll
        for (int k = 0; k < 16; k++) {
            const int ml = (k << 2) + sub;  // conflict-free: lanes hit consecutive m
            const float4 ga = gt_s[ml][0], gb = gt_s[ml][1];
            float s = fa.x * ga.x;
            s = fmaf(fa.y, ga.y, s); s = fmaf(fa.z, ga.z, s); s = fmaf(fa.w, ga.w, s);
            s = fmaf(fb.x, gb.x, s); s = fmaf(fb.y, gb.y, s);
            s = fmaf(fb.z, gb.z, s); s = fmaf(fb.w, gb.w, s);
            acc += __expf(s);
        }
    }
    acc += __shfl_down_sync(0xffffffffu, acc, 2);
    acc += __shfl_down_sync(0xffffffffu, acc, 1);
    if (sub == 0) d_invden[input * NTOK + n] = 1.0f / acc;
}

// ---------------------------------------------------------------------------
// Kernel 3: sa[c,m] = sum_n u[c,n] * exp(f[n].gt[m]),  u = v/den
//           y[c,m] = gamma*sa[c,m] + x[c,m]
// grid (128, 2), block 256. Block tile: 64 m x 64 c, n-tiles of 64.
// Thread: 4c x 4m register tile -> 16 FMA per 2 LDS.128 in the hot loop.
// ---------------------------------------------------------------------------
__global__ __launch_bounds__(256) void passB_kernel(
    const float* __restrict__ x1, const float* __restrict__ x2,
    const float* __restrict__ g1, const float* __restrict__ g2,
    float* __restrict__ out)
{
    const int input = blockIdx.y;
    const float* __restrict__ x = input ? x2 : x1;
    const float gamma = input ? g2[0] : g1[0];

    const int m_base = blockIdx.x * 64;
    const int tid = threadIdx.x;
    const int cg = tid >> 4, mg = tid & 15;
    const int c0 = cg * 4, m0l = mg * 4;

    __shared__ float  u_s[64][64];
    __shared__ float  e_s[64][64];
    __shared__ float4 f_s[64][2];
    __shared__ float4 gt_s[64][2];

    // this block's 64 gt[m] rows, loaded once
    if (tid < 128) {
        gt_s[tid >> 1][tid & 1] =
            ((const float4*)d_GT)[(size_t)(input * NTOK + m_base + (tid >> 1)) * 2 + (tid & 1)];
    }

    float acc[4][4];
    #pragma unroll
    for (int i = 0; i < 4; i++)
        #pragma unroll
        for (int j = 0; j < 4; j++) acc[i][j] = 0.f;

    const float*  VT  = d_VT + (size_t)input * NTOK * 64;
    const float*  INV = d_invden + input * NTOK;
    const float4* F4  = (const float4*)d_F;

    for (int n0 = 0; n0 < NTOK; n0 += 64) {
        __syncthreads();
        // u tile: u[n][c] = v[c,n] / den[n]   (coalesced)
        #pragma unroll
        for (int k = 0; k < 16; k++) {
            const int i = tid + k * 256;
            const int nl = i >> 6, c = i & 63;
            u_s[nl][c] = VT[(size_t)(n0 + nl) * 64 + c] * __ldg(&INV[n0 + nl]);
        }
        // f tile
        if (tid < 128) {
            f_s[tid >> 1][tid & 1] =
                F4[(size_t)(input * NTOK + n0 + (tid >> 1)) * 2 + (tid & 1)];
        }
        __syncthreads();
        // e tile: e[n][m] = exp(f[n].gt[m])
        #pragma unroll
        for (int k = 0; k < 16; k++) {
            const int i = tid + k * 256;
            const int nl = i >> 6, ml = i & 63;
            const float4 fa = f_s[nl][0], fb = f_s[nl][1];
            const float4 ga = gt_s[ml][0], gb = gt_s[ml][1];
            float s = fa.x * ga.x;
            s = fmaf(fa.y, ga.y, s); s = fmaf(fa.z, ga.z, s); s = fmaf(fa.w, ga.w, s);
            s = fmaf(fb.x, gb.x, s); s = fmaf(fb.y, gb.y, s);
            s = fmaf(fb.z, gb.z, s); s = fmaf(fb.w, gb.w, s);
            e_s[nl][ml] = __expf(s);
        }
        __syncthreads();
        // accumulate: 16 FMA per n per thread
        #pragma unroll 8
        for (int nl = 0; nl < 64; nl++) {
            const float4 u = *(const float4*)&u_s[nl][c0];
            const float4 e = *(const float4*)&e_s[nl][m0l];
            acc[0][0] = fmaf(u.x, e.x, acc[0][0]); acc[0][1] = fmaf(u.x, e.y, acc[0][1]);
            acc[0][2] = fmaf(u.x, e.z, acc[0][2]); acc[0][3] = fmaf(u.x, e.w, acc[0][3]);
            acc[1][0] = fmaf(u.y, e.x, acc[1][0]); acc[1][1] = fmaf(u.y, e.y, acc[1][1]);
            acc[1][2] = fmaf(u.y, e.z, acc[1][2]); acc[1][3] = fmaf(u.y, e.w, acc[1][3]);
            acc[2][0] = fmaf(u.z, e.x, acc[2][0]); acc[2][1] = fmaf(u.z, e.y, acc[2][1]);
            acc[2][2] = fmaf(u.z, e.z, acc[2][2]); acc[2][3] = fmaf(u.z, e.w, acc[2][3]);
            acc[3][0] = fmaf(u.w, e.x, acc[3][0]); acc[3][1] = fmaf(u.w, e.y, acc[3][1]);
            acc[3][2] = fmaf(u.w, e.z, acc[3][2]); acc[3][3] = fmaf(u.w, e.w, acc[3][3]);
        }
    }

    // epilogue: y = gamma * sa + x
    #pragma unroll
    for (int i = 0; i < 4; i++) {
        const int c = c0 + i;
        const float4 xv = *(const float4*)&x[(size_t)c * NTOK + m_base + m0l];
        float4 yv;
        yv.x = fmaf(gamma, acc[i][0], xv.x);
        yv.y = fmaf(gamma, acc[i][1], xv.y);
        yv.z = fmaf(gamma, acc[i][2], xv.z);
        yv.w = fmaf(gamma, acc[i][3], xv.w);
        *(float4*)&out[(size_t)(input * 64 + c) * NTOK + m_base + m0l] = yv;
    }
}

// ---------------------------------------------------------------------------
extern "C" void kernel_launch(void* const* d_in, const int* in_sizes, int n_in,
                              void* d_out, int out_size)
{
    (void)in_sizes; (void)n_in; (void)out_size;
    const float* x1  = (const float*)d_in[0];
    const float* x2  = (const float*)d_in[1];
    const float* Wf  = (const float*)d_in[2];
    const float* bf  = (const float*)d_in[3];
    const float* Wg  = (const float*)d_in[4];
    const float* bg  = (const float*)d_in[5];
    const float* Wh1 = (const float*)d_in[6];
    const float* bh1 = (const float*)d_in[7];
    const float* Wh2 = (const float*)d_in[8];
    const float* bh2 = (const float*)d_in[9];
    const float* g1  = (const float*)d_in[10];
    const float* g2  = (const float*)d_in[11];
    float* out = (float*)d_out;

    dim3 gp(NTOK / 128, 2);
    proj_kernel<<<gp, 128>>>(x1, x2, Wf, bf, Wg, bg, Wh1, bh1, Wh2, bh2);
    dim3 ga(NTOK / 64, 2);
    passA_kernel<<<ga, 256>>>();
    dim3 gb(NTOK / 64, 2);
    passB_kernel<<<gb, 256>>>(x1, x2, g1, g2, out);
}